// round 14
// baseline (speedup 1.0000x reference)
#include <cuda_runtime.h>

// TorchSTFT collapses analytically to an elementwise scale (see R1):
//   out[b,t] = x[b,t] * COLA(t+400) * invnorm
// COLA == 1.5 exactly for t in [200, 159800) (periodic Hann, 75% overlap);
// explicit partial COLA sum on the ~400 edge samples per row.
//
// R14 = R6/R13 (confirmed best, 9.02-9.06us) + STREAMING STORES (__stcs).
// Under graph replay the input stays L2-resident (reads ~free; HBM counter
// matches the write stream alone). Default write-allocate lets 20.5MB of
// output displace resident input lines; st.global.cs marks output
// evict-first so input residency survives. Loads stay default-cached
// (input IS reused across replays; .cs loads would be the wrong sign).

#define TIME      160000
#define BATCH     32
#define ROW_VEC   (TIME / 4)              // 40000 float4 per row
#define TOTAL_VEC (BATCH * ROW_VEC)       // 1,280,000
#define TPB       256
#define NBLOCKS   1184                    // 148 SMs * 8 blocks/SM, one wave
#define GSTRIDE   (NBLOCKS * TPB)         // 303,104 threads
#define VPT       4
// 4*GSTRIDE = 1,212,416 ; tail = 67,584 vectors -> threads [0, 67584)

// invnorm = sqrt(1 - 0.25 + 1e-8)
#define INVNORM_F 0.86602540956f
// interior gain = 1.5 * invnorm
#define CGAIN_F   1.29903811433f

// Exact partial COLA gain (float). Valid for all t; used only on edge vectors.
__device__ __forceinline__ float edge_gain(int t) {
    int p = t + 400;                          // OLA-coordinate position
    int fmin = (p > 799) ? (p - 799 + 199) / 200 : 0;
    int fmax = p / 200;
    if (fmax > 800) fmax = 800;               // F-1 = 800
    float s = 0.0f;
    for (int f = fmin; f <= fmax; ++f) {
        int n = p - 200 * f;                  // 0..799
        // hann_periodic(n) = 0.5 - 0.5*cospi(n/400)
        float w = 0.5f - 0.5f * cospif((float)n * (1.0f / 400.0f));
        s += w * w;
    }
    return s * INVNORM_F;
}

__device__ __forceinline__ void scale_vec(float4& v, int idx) {
    int row = idx / ROW_VEC;
    int t0  = (idx - row * ROW_VEC) * 4;      // element offset within row
    if (t0 >= 200 && t0 <= 159796) {          // whole vector in COLA interior
        v.x *= CGAIN_F;
        v.y *= CGAIN_F;
        v.z *= CGAIN_F;
        v.w *= CGAIN_F;
    } else {
        v.x *= edge_gain(t0);
        v.y *= edge_gain(t0 + 1);
        v.z *= edge_gain(t0 + 2);
        v.w *= edge_gain(t0 + 3);
    }
}

__global__ void __launch_bounds__(TPB)
torchstft_scale_kernel(const float4* __restrict__ in, float4* __restrict__ out) {
    int tid = blockIdx.x * TPB + threadIdx.x;

    // Batch all loads first: 4 (+1 conditional) independent LDG.128 in flight.
    float4 v[VPT];
#pragma unroll
    for (int k = 0; k < VPT; ++k)
        v[k] = in[tid + k * GSTRIDE];

    int tail_idx = tid + VPT * GSTRIDE;
    bool has_tail = tail_idx < TOTAL_VEC;
    float4 vt;
    if (has_tail) vt = in[tail_idx];

#pragma unroll
    for (int k = 0; k < VPT; ++k) {
        int idx = tid + k * GSTRIDE;
        scale_vec(v[k], idx);
        __stcs(&out[idx], v[k]);              // streaming store: evict-first
    }
    if (has_tail) {
        scale_vec(vt, tail_idx);
        __stcs(&out[tail_idx], vt);
    }
}

extern "C" void kernel_launch(void* const* d_in, const int* in_sizes, int n_in,
                              void* d_out, int out_size) {
    (void)in_sizes; (void)n_in; (void)out_size;
    const float4* in = (const float4*)d_in[0];
    float4* out = (float4*)d_out;
    torchstft_scale_kernel<<<NBLOCKS, TPB>>>(in, out);
}

// round 16
// speedup vs baseline: 1.0179x; 1.0179x over previous
#include <cuda_runtime.h>

// TorchSTFT collapses analytically to an elementwise scale (see R1):
//   STFT -> mag/phase -> resynth is exact (sre=re, sim=im); the Hermitian
//   inverse DFT of a real frame is an exact identity; OLA at position p only
//   touches x_pad[p]. Hence:
//     out[b,t] = x[b,t] * COLA(t+400) * invnorm
//   with COLA == 1.5 exactly for t in [200, 159800) (periodic Hann, HOP=200,
//   WIN=800 -> 75% overlap), and an explicit partial COLA sum on the ~400
//   edge samples per row.
//
// FINAL (== R13, best measured 9.02-9.06us, reproduced twice):
//   - single full-occupancy wave: 148 SMs x 8 blocks = 1184 blocks x 256 thr
//   - 4 front-batched LDG.128 per thread at stride G + 1 conditional tail
//     (the measured MLP/occupancy optimum; deeper batching, forced
//     residency, split batches, bulk-TMA, and streaming stores all measured
//     equal-or-worse: the kernel sits at the transfer + replay-ramp floor,
//     every memory counter ~25%-of-elapsed).

#define TIME      160000
#define BATCH     32
#define ROW_VEC   (TIME / 4)              // 40000 float4 per row
#define TOTAL_VEC (BATCH * ROW_VEC)       // 1,280,000
#define TPB       256
#define NBLOCKS   1184                    // 148 SMs * 8 blocks/SM
#define GSTRIDE   (NBLOCKS * TPB)         // 303,104 threads
#define VPT       4
// 4*GSTRIDE = 1,212,416 ; tail = 67,584 vectors -> threads [0, 67584)

// invnorm = sqrt(1 - 0.25 + 1e-8)
#define INVNORM_F 0.86602540956f
// interior gain = 1.5 * invnorm
#define CGAIN_F   1.29903811433f

// Exact partial COLA gain (float). Valid for all t; used only on edge vectors.
__device__ __forceinline__ float edge_gain(int t) {
    int p = t + 400;                          // OLA-coordinate position
    int fmin = (p > 799) ? (p - 799 + 199) / 200 : 0;
    int fmax = p / 200;
    if (fmax > 800) fmax = 800;               // F-1 = 800
    float s = 0.0f;
    for (int f = fmin; f <= fmax; ++f) {
        int n = p - 200 * f;                  // 0..799
        // hann_periodic(n) = 0.5 - 0.5*cospi(n/400)
        float w = 0.5f - 0.5f * cospif((float)n * (1.0f / 400.0f));
        s += w * w;
    }
    return s * INVNORM_F;
}

__device__ __forceinline__ void scale_vec(float4& v, int idx) {
    int row = idx / ROW_VEC;
    int t0  = (idx - row * ROW_VEC) * 4;      // element offset within row
    if (t0 >= 200 && t0 <= 159796) {          // whole vector in COLA interior
        v.x *= CGAIN_F;
        v.y *= CGAIN_F;
        v.z *= CGAIN_F;
        v.w *= CGAIN_F;
    } else {
        v.x *= edge_gain(t0);
        v.y *= edge_gain(t0 + 1);
        v.z *= edge_gain(t0 + 2);
        v.w *= edge_gain(t0 + 3);
    }
}

__global__ void __launch_bounds__(TPB)
torchstft_scale_kernel(const float4* __restrict__ in, float4* __restrict__ out) {
    int tid = blockIdx.x * TPB + threadIdx.x;

    // Batch all loads first: 4 (+1 conditional) independent LDG.128 in flight.
    float4 v[VPT];
#pragma unroll
    for (int k = 0; k < VPT; ++k)
        v[k] = in[tid + k * GSTRIDE];

    int tail_idx = tid + VPT * GSTRIDE;
    bool has_tail = tail_idx < TOTAL_VEC;
    float4 vt;
    if (has_tail) vt = in[tail_idx];

#pragma unroll
    for (int k = 0; k < VPT; ++k) {
        int idx = tid + k * GSTRIDE;
        scale_vec(v[k], idx);
        out[idx] = v[k];
    }
    if (has_tail) {
        scale_vec(vt, tail_idx);
        out[tail_idx] = vt;
    }
}

extern "C" void kernel_launch(void* const* d_in, const int* in_sizes, int n_in,
                              void* d_out, int out_size) {
    (void)in_sizes; (void)n_in; (void)out_size;
    const float4* in = (const float4*)d_in[0];
    float4* out = (float4*)d_out;
    torchstft_scale_kernel<<<NBLOCKS, TPB>>>(in, out);
}